// round 1
// baseline (speedup 1.0000x reference)
#include <cuda_runtime.h>
#include <math.h>

// Problem constants
constexpr int B_  = 8;
constexpr int C_  = 256;
constexpr int H_  = 31;
constexpr int W_  = 31;
constexpr int T_  = 7;
constexpr int K_  = 49;      // T*T
constexpr int OC_ = 147;     // 3*K
constexpr int OH_ = 25;      // H - T + 1
constexpr int OW_ = 25;
constexpr int HW_ = H_ * W_; // 961

// Scratch (no allocations allowed -> device globals)
__device__ float g_srT[B_ * HW_ * C_];    // (B, H, W, C)  ~7.9MB
__device__ float g_tmplT[B_ * K_ * C_];   // (B, K, C)
__device__ float g_om[B_ * OC_ * OH_ * OW_]; // conv output, cropped 25x25

// ---------------------------------------------------------------------------
// K1: transpose sr (B,C,H*W) -> (B,H*W,C)
// ---------------------------------------------------------------------------
__global__ void transpose_sr_kernel(const float* __restrict__ sr) {
    __shared__ float tile[32][33];
    int b  = blockIdx.z;
    int p0 = blockIdx.x * 32;   // spatial
    int c0 = blockIdx.y * 32;   // channel
    int tx = threadIdx.x, ty = threadIdx.y;

    #pragma unroll
    for (int yy = 0; yy < 32; yy += 8) {
        int c = c0 + ty + yy;
        int p = p0 + tx;
        if (p < HW_)
            tile[ty + yy][tx] = sr[(b * C_ + c) * HW_ + p];
    }
    __syncthreads();
    #pragma unroll
    for (int yy = 0; yy < 32; yy += 8) {
        int p = p0 + ty + yy;
        int c = c0 + tx;
        if (p < HW_)
            g_srT[(b * HW_ + p) * C_ + c] = tile[tx][ty + yy];
    }
}

// ---------------------------------------------------------------------------
// K1b: transpose tmpl (B,C,K) -> (B,K,C)
// ---------------------------------------------------------------------------
__global__ void transpose_tmpl_kernel(const float* __restrict__ tmpl) {
    int t = blockIdx.x * 256 + threadIdx.x;
    if (t < B_ * K_ * C_) {
        int c = t % C_;
        int k = (t / C_) % K_;
        int b = t / (C_ * K_);
        g_tmplT[t] = tmpl[(b * C_ + c) * K_ + k];
    }
}

// ---------------------------------------------------------------------------
// K2: 3x3 SAME conv, only cropped 25x25 output region.
// grid = (OH_, B_), block = 256 threads (245 active).
// Thread tile: 3 output channels x 5 output x positions.
// Reduction over C in chunks of 8 channels staged through smem.
// ---------------------------------------------------------------------------
__global__ void __launch_bounds__(256) conv_om_kernel(
    const float* __restrict__ sr,
    const float* __restrict__ w,     // (147,256,3,3)
    const float* __restrict__ bias)  // (147,)
{
    __shared__ float s_sr[8][3][33];        // 8 ch x 3 rows x padded width 33 (cols -1..31)
    __shared__ float s_w[OC_ * 72];         // [o*72 + cc*9 + t]

    const int y   = blockIdx.x;
    const int b   = blockIdx.y;
    const int tid = threadIdx.x;

    const int og = tid / 5;         // 0..50 (49 active)
    const int xg = tid % 5;
    const bool active = (og < 49);
    const int o_base = og * 3;
    const int x_base = xg * 5;

    float acc[3][5];
    #pragma unroll
    for (int a = 0; a < 3; a++)
        #pragma unroll
        for (int x = 0; x < 5; x++) acc[a][x] = 0.f;

    for (int c0 = 0; c0 < C_; c0 += 8) {
        __syncthreads();
        // stage sr rows y-1..y+1, padded cols
        for (int e = tid; e < 8 * 3 * 33; e += 256) {
            int cc  = e / 99;
            int rem = e % 99;
            int r   = rem / 33;
            int xp  = rem % 33;
            int gy  = y + r - 1;
            int gx  = xp - 1;
            float v = 0.f;
            if (gy >= 0 && gx >= 0 && gx < W_)
                v = sr[((b * C_ + c0 + cc) * H_ + gy) * W_ + gx];
            s_sr[cc][r][xp] = v;
        }
        // stage weights for this channel chunk
        for (int e = tid; e < OC_ * 72; e += 256) {
            int o   = e / 72;
            int rem = e % 72;
            s_w[e] = w[o * (C_ * 9) + c0 * 9 + rem];
        }
        __syncthreads();

        if (active) {
            #pragma unroll
            for (int cc = 0; cc < 8; cc++) {
                float r0[7], r1[7], r2[7];
                #pragma unroll
                for (int u = 0; u < 7; u++) {
                    r0[u] = s_sr[cc][0][x_base + u];
                    r1[u] = s_sr[cc][1][x_base + u];
                    r2[u] = s_sr[cc][2][x_base + u];
                }
                #pragma unroll
                for (int oo = 0; oo < 3; oo++) {
                    const float* wp = &s_w[(o_base + oo) * 72 + cc * 9];
                    float w0 = wp[0], w1 = wp[1], w2 = wp[2];
                    float w3 = wp[3], w4 = wp[4], w5 = wp[5];
                    float w6 = wp[6], w7 = wp[7], w8 = wp[8];
                    #pragma unroll
                    for (int xx = 0; xx < 5; xx++) {
                        float a = acc[oo][xx];
                        a = fmaf(r0[xx    ], w0, a);
                        a = fmaf(r0[xx + 1], w1, a);
                        a = fmaf(r0[xx + 2], w2, a);
                        a = fmaf(r1[xx    ], w3, a);
                        a = fmaf(r1[xx + 1], w4, a);
                        a = fmaf(r1[xx + 2], w5, a);
                        a = fmaf(r2[xx    ], w6, a);
                        a = fmaf(r2[xx + 1], w7, a);
                        a = fmaf(r2[xx + 2], w8, a);
                        acc[oo][xx] = a;
                    }
                }
            }
        }
    }

    if (active) {
        #pragma unroll
        for (int oo = 0; oo < 3; oo++) {
            int o = o_base + oo;
            float bb = bias[o];
            #pragma unroll
            for (int xx = 0; xx < 5; xx++) {
                g_om[((b * OC_ + o) * OH_ + y) * OW_ + x_base + xx] = acc[oo][xx] + bb;
            }
        }
    }
}

// ---------------------------------------------------------------------------
// K3: deformable bilinear gather + weighted correlation.
// grid = (OW_, OH_, B_), block = 256 threads (= C).
// Phase 1 (threads 0..48): per-k metadata -> smem (4 clamped corner offsets,
//   4 corner weights = bilinear * valid * sigmoid(mask)).
// Phase 2: thread c accumulates over k with coalesced loads from g_srT/g_tmplT.
// ---------------------------------------------------------------------------
__global__ void __launch_bounds__(256) deform_xcorr_kernel(float* __restrict__ out)
{
    __shared__ int   sA[4][K_];
    __shared__ float sW[4][K_];

    const int j = blockIdx.x;
    const int i = blockIdx.y;
    const int b = blockIdx.z;
    const int tid = threadIdx.x;

    if (tid < K_) {
        const int k = tid;
        const int base = ((b * OC_ + k) * OH_ + i) * OW_ + j;
        float oy = g_om[base];
        float ox = g_om[base + 49 * (OH_ * OW_)];
        float mz = g_om[base + 98 * (OH_ * OW_)];
        float m  = 1.0f / (1.0f + __expf(-mz));

        float ys = (float)i + (float)(k / T_) + oy;
        float xs = (float)j + (float)(k % T_) + ox;
        float y0f = floorf(ys), x0f = floorf(xs);
        float wy = ys - y0f, wx = xs - x0f;
        float y1f = y0f + 1.0f, x1f = x0f + 1.0f;

        bool vy0 = (y0f >= 0.0f) && (y0f <= (float)(H_ - 1));
        bool vy1 = (y1f >= 0.0f) && (y1f <= (float)(H_ - 1));
        bool vx0 = (x0f >= 0.0f) && (x0f <= (float)(W_ - 1));
        bool vx1 = (x1f >= 0.0f) && (x1f <= (float)(W_ - 1));

        float w00 = (1.0f - wy) * (1.0f - wx) * m; if (!(vy0 && vx0)) w00 = 0.0f;
        float w01 = (1.0f - wy) * wx          * m; if (!(vy0 && vx1)) w01 = 0.0f;
        float w10 = wy          * (1.0f - wx) * m; if (!(vy1 && vx0)) w10 = 0.0f;
        float w11 = wy          * wx          * m; if (!(vy1 && vx1)) w11 = 0.0f;

        int y0 = (int)fminf(fmaxf(y0f, 0.0f), (float)(H_ - 1));
        int y1 = (int)fminf(fmaxf(y1f, 0.0f), (float)(H_ - 1));
        int x0 = (int)fminf(fmaxf(x0f, 0.0f), (float)(W_ - 1));
        int x1 = (int)fminf(fmaxf(x1f, 0.0f), (float)(W_ - 1));

        sA[0][k] = (y0 * W_ + x0) * C_;
        sA[1][k] = (y0 * W_ + x1) * C_;
        sA[2][k] = (y1 * W_ + x0) * C_;
        sA[3][k] = (y1 * W_ + x1) * C_;
        sW[0][k] = w00; sW[1][k] = w01; sW[2][k] = w10; sW[3][k] = w11;
    }
    __syncthreads();

    const int c = tid;
    const float* __restrict__ srTb = g_srT + (size_t)b * HW_ * C_;
    const float* __restrict__ tTb  = g_tmplT + (size_t)b * K_ * C_;

    float acc = 0.0f;
    #pragma unroll 7
    for (int k = 0; k < K_; k++) {
        float tv = tTb[k * C_ + c];
        float v;
        v = sW[0][k] * srTb[sA[0][k] + c];
        v = fmaf(sW[1][k], srTb[sA[1][k] + c], v);
        v = fmaf(sW[2][k], srTb[sA[2][k] + c], v);
        v = fmaf(sW[3][k], srTb[sA[3][k] + c], v);
        acc = fmaf(tv, v, acc);
    }

    out[((b * C_ + c) * OH_ + i) * OW_ + j] = acc;
}

// ---------------------------------------------------------------------------
extern "C" void kernel_launch(void* const* d_in, const int* in_sizes, int n_in,
                              void* d_out, int out_size)
{
    const float* sr   = (const float*)d_in[0];  // (8,256,31,31)
    const float* tmpl = (const float*)d_in[1];  // (8,256,7,7)
    const float* w    = (const float*)d_in[2];  // (147,256,3,3)
    const float* bias = (const float*)d_in[3];  // (147,)
    float* out = (float*)d_out;                 // (8,256,25,25)

    {
        dim3 tb(32, 8);
        dim3 tg((HW_ + 31) / 32, C_ / 32, B_);
        transpose_sr_kernel<<<tg, tb>>>(sr);
    }
    {
        int n = B_ * K_ * C_;
        transpose_tmpl_kernel<<<(n + 255) / 256, 256>>>(tmpl);
    }
    {
        dim3 g(OH_, B_);
        conv_om_kernel<<<g, 256>>>(sr, w, bias);
    }
    {
        dim3 g(OW_, OH_, B_);
        deform_xcorr_kernel<<<g, 256>>>(out);
    }
}

// round 2
// speedup vs baseline: 1.7684x; 1.7684x over previous
#include <cuda_runtime.h>
#include <math.h>

// Problem constants
constexpr int B_  = 8;
constexpr int C_  = 256;
constexpr int H_  = 31;
constexpr int W_  = 31;
constexpr int T_  = 7;
constexpr int K_  = 49;      // T*T
constexpr int OC_ = 147;     // 3*K
constexpr int OCP_= 148;     // padded to even
constexpr int NP_ = 74;      // oc pairs
constexpr int OH_ = 25;
constexpr int OW_ = 25;
constexpr int HW_ = H_ * W_; // 961
constexpr int OHW_= OH_ * OW_; // 625
constexpr int CT_ = 4;       // C split tiles
constexpr int CPT_= C_ / CT_;// 64 channels per tile
constexpr int YT_ = 13;      // y tiles of 2 rows

// Scratch (device globals; no allocations allowed)
__device__ float g_srT[B_ * HW_ * C_];                 // (B,H,W,C)
__device__ float g_tmplT[B_ * K_ * C_];                // (B,K,C)
__device__ float g_om[B_ * OC_ * OHW_];                // conv out (b,oc,y,x)
__device__ float g_part[CT_ * B_ * OC_ * OHW_];        // conv partials
__device__ float2 g_wpk[C_ * NP_ * 9];                 // packed weights [c][pair][tap]

// packed f32x2 helpers
#define FMA_F32X2(d, a, b, c) \
    asm("fma.rn.f32x2 %0, %1, %2, %3;" : "=l"(d) : "l"(a), "l"(b), "l"(c))
#define PACK_DUP(d, v) \
    asm("mov.b64 %0, {%1, %1};" : "=l"(d) : "f"(v))
#define UNPACK2(lo, hi, p) \
    asm("mov.b64 {%0, %1}, %2;" : "=f"(lo), "=f"(hi) : "l"(p))

// ---------------------------------------------------------------------------
// transpose sr (B,C,HW) -> (B,HW,C)
// ---------------------------------------------------------------------------
__global__ void transpose_sr_kernel(const float* __restrict__ sr) {
    __shared__ float tile[32][33];
    int b  = blockIdx.z;
    int p0 = blockIdx.x * 32;
    int c0 = blockIdx.y * 32;
    int tx = threadIdx.x, ty = threadIdx.y;
    #pragma unroll
    for (int yy = 0; yy < 32; yy += 8) {
        int c = c0 + ty + yy, p = p0 + tx;
        if (p < HW_) tile[ty + yy][tx] = sr[(b * C_ + c) * HW_ + p];
    }
    __syncthreads();
    #pragma unroll
    for (int yy = 0; yy < 32; yy += 8) {
        int p = p0 + ty + yy, c = c0 + tx;
        if (p < HW_) g_srT[(b * HW_ + p) * C_ + c] = tile[tx][ty + yy];
    }
}

// transpose tmpl (B,C,K) -> (B,K,C)
__global__ void transpose_tmpl_kernel(const float* __restrict__ tmpl) {
    int t = blockIdx.x * 256 + threadIdx.x;
    if (t < B_ * K_ * C_) {
        int c = t % C_;
        int k = (t / C_) % K_;
        int b = t / (C_ * K_);
        g_tmplT[t] = tmpl[(b * C_ + c) * K_ + k];
    }
}

// ---------------------------------------------------------------------------
// pack conv weights: (147,256,3,3) -> g_wpk[c][pair][tap] float2 (oc even/odd)
// ---------------------------------------------------------------------------
__global__ void pack_weights_kernel(const float* __restrict__ w) {
    int t = blockIdx.x * 256 + threadIdx.x;     // over C_*NP_*9 = 170496
    if (t < C_ * NP_ * 9) {
        int tap = t % 9;
        int p   = (t / 9) % NP_;
        int c   = t / (9 * NP_);
        int o0 = 2 * p, o1 = 2 * p + 1;
        float v0 = w[o0 * (C_ * 9) + c * 9 + tap];
        float v1 = (o1 < OC_) ? w[o1 * (C_ * 9) + c * 9 + tap] : 0.0f;
        g_wpk[t] = make_float2(v0, v1);
    }
}

// ---------------------------------------------------------------------------
// K2: 3x3 conv on cropped region, f32x2 packed math, split-C partials.
// grid = (YT_=13, B_=8, CT_=4), block = 256.
// Thread (tid<185): og=tid/5 (0..36) -> 4 oc (2 pairs), xg=tid%5 -> 5 x.
// Each block: 2 output rows, 64-channel slice, all 148 (padded) oc.
// ---------------------------------------------------------------------------
__global__ void __launch_bounds__(256) conv_om_kernel(
    const float* __restrict__ sr)
{
    __shared__ float  s_sr[8][4][33];            // 8 ch x 4 rows x cols -1..31
    __shared__ float2 s_wp[8 * NP_ * 9];         // [cc][pair][tap]

    const int by = blockIdx.x;
    const int b  = blockIdx.y;
    const int ct = blockIdx.z;
    const int tid = threadIdx.x;

    const int og = tid / 5;
    const int xg = tid % 5;
    const bool active = (tid < 185);
    const int x_base = xg * 5;
    const int y_base = by * 2;
    const int cbase  = ct * CPT_;

    unsigned long long acc[2][2][5];             // [pair][yy][xx]
    #pragma unroll
    for (int pp = 0; pp < 2; pp++)
        #pragma unroll
        for (int yy = 0; yy < 2; yy++)
            #pragma unroll
            for (int xx = 0; xx < 5; xx++) acc[pp][yy][xx] = 0ull;

    for (int ch = 0; ch < CPT_; ch += 8) {
        const int c0 = cbase + ch;
        __syncthreads();
        // stage sr rows y_base-1 .. y_base+2, padded cols -1..31
        for (int e = tid; e < 8 * 4 * 33; e += 256) {
            int cc  = e / 132;
            int rem = e % 132;
            int r   = rem / 33;
            int xp  = rem % 33;
            int gy  = y_base + r - 1;
            int gx  = xp - 1;
            float v = 0.f;
            if (gy >= 0 && gy < H_ && gx >= 0 && gx < W_)
                v = sr[((b * C_ + c0 + cc) * H_ + gy) * W_ + gx];
            s_sr[cc][r][xp] = v;
        }
        // stage packed weights: contiguous copy of 8*NP_*9 float2
        {
            const float4* src = (const float4*)(&g_wpk[c0 * NP_ * 9]);
            float4* dst = (float4*)s_wp;
            for (int e = tid; e < 8 * NP_ * 9 / 2; e += 256)
                dst[e] = src[e];
        }
        __syncthreads();

        if (active) {
            #pragma unroll
            for (int cc = 0; cc < 8; cc++) {
                // weights for this thread's 2 pairs
                unsigned long long wq[2][9];
                #pragma unroll
                for (int pp = 0; pp < 2; pp++) {
                    const unsigned long long* wp =
                        (const unsigned long long*)&s_wp[(cc * NP_ + og * 2 + pp) * 9];
                    #pragma unroll
                    for (int t = 0; t < 9; t++) wq[pp][t] = wp[t];
                }
                #pragma unroll
                for (int ir = 0; ir < 4; ir++) {
                    unsigned long long rp[7];
                    #pragma unroll
                    for (int u = 0; u < 7; u++) {
                        float v = s_sr[cc][ir][x_base + u];
                        PACK_DUP(rp[u], v);
                    }
                    #pragma unroll
                    for (int dy = 0; dy < 3; dy++) {
                        int yy = ir - dy;
                        if (yy >= 0 && yy < 2) {
                            #pragma unroll
                            for (int pp = 0; pp < 2; pp++)
                                #pragma unroll
                                for (int dx = 0; dx < 3; dx++)
                                    #pragma unroll
                                    for (int xx = 0; xx < 5; xx++)
                                        FMA_F32X2(acc[pp][yy][xx],
                                                  rp[xx + dx],
                                                  wq[pp][dy * 3 + dx],
                                                  acc[pp][yy][xx]);
                        }
                    }
                }
            }
        }
    }

    if (active) {
        #pragma unroll
        for (int pp = 0; pp < 2; pp++) {
            int o_even = og * 4 + pp * 2;
            #pragma unroll
            for (int yy = 0; yy < 2; yy++) {
                int y = y_base + yy;
                if (y >= OH_) continue;
                #pragma unroll
                for (int xx = 0; xx < 5; xx++) {
                    float lo, hi;
                    UNPACK2(lo, hi, acc[pp][yy][xx]);
                    int base = ct * (B_ * OC_ * OHW_) +
                               (b * OC_ + o_even) * OHW_ + y * OW_ + x_base + xx;
                    g_part[base] = lo;
                    if (o_even + 1 < OC_) g_part[base + OHW_] = hi;
                }
            }
        }
    }
}

// sum partials + bias -> g_om
__global__ void reduce_om_kernel(const float* __restrict__ bias) {
    int t = blockIdx.x * 256 + threadIdx.x;
    if (t < B_ * OC_ * OHW_) {
        int oc = (t / OHW_) % OC_;
        float s = bias[oc];
        #pragma unroll
        for (int ct = 0; ct < CT_; ct++)
            s += g_part[ct * (B_ * OC_ * OHW_) + t];
        g_om[t] = s;
    }
}

// ---------------------------------------------------------------------------
// K3: deformable bilinear gather + weighted correlation (vectorized).
// grid = 1250 blocks, block = 256 threads = 4 groups x 64 threads.
// Group g handles position p = blockIdx.x*4 + g; thread = 4 channels (float4).
// ---------------------------------------------------------------------------
__global__ void __launch_bounds__(256) deform_xcorr_kernel(float* __restrict__ out)
{
    __shared__ int4   sA4[4][K_];   // byte offsets of 4 corners
    __shared__ float4 sW4[4][K_];   // folded weights (bilinear*valid*mask)

    const int tid = threadIdx.x;

    // metadata phase: 196 threads, one per (group,k)
    if (tid < 4 * K_) {
        const int g2 = tid / K_;
        const int k  = tid % K_;
        const int p  = blockIdx.x * 4 + g2;
        const int b  = p / OHW_;
        const int rem = p % OHW_;
        const int i  = rem / OW_;
        const int j  = rem % OW_;

        const int base = (b * OC_ + k) * OHW_ + i * OW_ + j;
        float oy = g_om[base];
        float ox = g_om[base + 49 * OHW_];
        float mz = g_om[base + 98 * OHW_];
        float m  = 1.0f / (1.0f + __expf(-mz));

        float ys = (float)i + (float)(k / T_) + oy;
        float xs = (float)j + (float)(k % T_) + ox;
        float y0f = floorf(ys), x0f = floorf(xs);
        float wy = ys - y0f, wx = xs - x0f;
        float y1f = y0f + 1.0f, x1f = x0f + 1.0f;

        bool vy0 = (y0f >= 0.0f) && (y0f <= (float)(H_ - 1));
        bool vy1 = (y1f >= 0.0f) && (y1f <= (float)(H_ - 1));
        bool vx0 = (x0f >= 0.0f) && (x0f <= (float)(W_ - 1));
        bool vx1 = (x1f >= 0.0f) && (x1f <= (float)(W_ - 1));

        float w00 = (1.0f - wy) * (1.0f - wx) * m; if (!(vy0 && vx0)) w00 = 0.0f;
        float w01 = (1.0f - wy) * wx          * m; if (!(vy0 && vx1)) w01 = 0.0f;
        float w10 = wy          * (1.0f - wx) * m; if (!(vy1 && vx0)) w10 = 0.0f;
        float w11 = wy          * wx          * m; if (!(vy1 && vx1)) w11 = 0.0f;

        int y0 = (int)fminf(fmaxf(y0f, 0.0f), (float)(H_ - 1));
        int y1 = (int)fminf(fmaxf(y1f, 0.0f), (float)(H_ - 1));
        int x0 = (int)fminf(fmaxf(x0f, 0.0f), (float)(W_ - 1));
        int x1 = (int)fminf(fmaxf(x1f, 0.0f), (float)(W_ - 1));

        sA4[g2][k] = make_int4((y0 * W_ + x0) * (C_ * 4),
                               (y0 * W_ + x1) * (C_ * 4),
                               (y1 * W_ + x0) * (C_ * 4),
                               (y1 * W_ + x1) * (C_ * 4));
        sW4[g2][k] = make_float4(w00, w01, w10, w11);
    }
    __syncthreads();

    const int g  = tid / 64;
    const int c4 = tid % 64;
    const int p  = blockIdx.x * 4 + g;
    const int b  = p / OHW_;
    const int rem = p % OHW_;
    const int i  = rem / OW_;
    const int j  = rem % OW_;

    const char* srTb = (const char*)(g_srT + (size_t)b * HW_ * C_) + c4 * 16;
    const float4* tT = (const float4*)(g_tmplT + (size_t)b * K_ * C_) + c4;

    float4 acc = make_float4(0.f, 0.f, 0.f, 0.f);
    #pragma unroll 7
    for (int k = 0; k < K_; k++) {
        int4   a  = sA4[g][k];
        float4 wv = sW4[g][k];
        float4 v00 = *(const float4*)(srTb + a.x);
        float4 v01 = *(const float4*)(srTb + a.y);
        float4 v10 = *(const float4*)(srTb + a.z);
        float4 v11 = *(const float4*)(srTb + a.w);
        float4 tv  = tT[(size_t)k * 64];

        float sx, sy, sz, sw;
        sx = wv.x * v00.x; sx = fmaf(wv.y, v01.x, sx); sx = fmaf(wv.z, v10.x, sx); sx = fmaf(wv.w, v11.x, sx);
        sy = wv.x * v00.y; sy = fmaf(wv.y, v01.y, sy); sy = fmaf(wv.z, v10.y, sy); sy = fmaf(wv.w, v11.y, sy);
        sz = wv.x * v00.z; sz = fmaf(wv.y, v01.z, sz); sz = fmaf(wv.z, v10.z, sz); sz = fmaf(wv.w, v11.z, sz);
        sw = wv.x * v00.w; sw = fmaf(wv.y, v01.w, sw); sw = fmaf(wv.z, v10.w, sw); sw = fmaf(wv.w, v11.w, sw);

        acc.x = fmaf(tv.x, sx, acc.x);
        acc.y = fmaf(tv.y, sy, acc.y);
        acc.z = fmaf(tv.z, sz, acc.z);
        acc.w = fmaf(tv.w, sw, acc.w);
    }

    const int c = c4 * 4;
    float* op = out + ((size_t)(b * C_ + c) * OH_ + i) * OW_ + j;
    op[0]           = acc.x;
    op[OHW_]        = acc.y;
    op[2 * OHW_]    = acc.z;
    op[3 * OHW_]    = acc.w;
}

// ---------------------------------------------------------------------------
extern "C" void kernel_launch(void* const* d_in, const int* in_sizes, int n_in,
                              void* d_out, int out_size)
{
    const float* sr   = (const float*)d_in[0];
    const float* tmpl = (const float*)d_in[1];
    const float* w    = (const float*)d_in[2];
    const float* bias = (const float*)d_in[3];
    float* out = (float*)d_out;

    {
        dim3 tb(32, 8);
        dim3 tg((HW_ + 31) / 32, C_ / 32, B_);
        transpose_sr_kernel<<<tg, tb>>>(sr);
    }
    {
        int n = B_ * K_ * C_;
        transpose_tmpl_kernel<<<(n + 255) / 256, 256>>>(tmpl);
    }
    {
        int n = C_ * NP_ * 9;
        pack_weights_kernel<<<(n + 255) / 256, 256>>>(w);
    }
    {
        dim3 g(YT_, B_, CT_);
        conv_om_kernel<<<g, 256>>>(sr);
    }
    {
        int n = B_ * OC_ * OHW_;
        reduce_om_kernel<<<(n + 255) / 256, 256>>>(bias);
    }
    {
        deform_xcorr_kernel<<<1250, 256>>>(out);
    }
}